// round 14
// baseline (speedup 1.0000x reference)
#include <cuda_runtime.h>
#include <cooperative_groups.h>
#include <cstdint>

namespace cg = cooperative_groups;

// ---------------------------------------------------------------------------
// VectorBasis: out[a,m,o] = sum_{edges e with center a}
//     fc(d_e) * Y_m(e) * sum_n R_n(d_e) * T[sc_a, sn_e, n, o]
// where T[sc,sn,n,o] = sum_q W_alch[sn,q] * emb[sc, n*4+q] * Wc[o, n*4+q]
//
// R14: ONE cooperative persistent kernel (3 phases, 2 hardware grid syncs):
//   phase 0: pack species->u8 (grid-stride)
//   phase 1: edge tiles (grid-stride over EPB tiles; R12-proven body:
//            direct LDG.128 loads, scalar Chebyshev, 3x red.v4)
//   phase 2: flat finalize + zero-writeback (restores scratch==0 invariant)
// No live state across grid.sync (R13 lesson). Grid sized via occupancy API
// so all blocks are co-resident (cooperative launch requirement).
// Scratch layout: padded m-rows scratch[a*12 + m*4 + o], lane 3 = pad.
// ---------------------------------------------------------------------------

#define A_MAX 100000
__device__ float         g_scratch[A_MAX * 12];   // zero at load; invariant kept by phase 2
__device__ unsigned char g_spec8[A_MAX + 4];

__device__ __forceinline__ void red_add_v4(float* p, float a, float b, float c, float d) {
    asm volatile("red.global.add.v4.f32 [%0], {%1, %2, %3, %4};"
                 :: "l"(p), "f"(a), "f"(b), "f"(c), "f"(d)
                 : "memory");
}

#define EPB 1024   // edges per tile (256 threads x 4)

__device__ __forceinline__ void process_edge(
    float vx, float vy, float vz, int a, int nb,
    const unsigned char* __restrict__ spec8,
    const float* __restrict__ sT,
    float* __restrict__ scratch)
{
    float d2   = fmaf(vx, vx, fmaf(vy, vy, vz * vz)) + 1e-12f;
    float invd = rsqrtf(d2);
    float d    = d2 * invd;

    int sc = (int)__ldg(&spec8[a]);
    int sn = (int)__ldg(&spec8[nb]);
    const float* T = &sT[(sc * 4 + sn) * 25];

    // R_n = sin(n*pi*d/rc)/d via scalar Chebyshev recurrence
    float s, c;
    __sincosf(0.62831853071795864769f * d, &s, &c);  // pi/5 * d
    float twoc = 2.0f * c;
    float r_nm1 = 0.0f;
    float r_n   = s * invd;

    float h0 = 0.f, h1 = 0.f, h2 = 0.f;
#pragma unroll
    for (int n = 0; n < 8; n++) {
        h0 = fmaf(r_n, T[n * 3 + 0], h0);
        h1 = fmaf(r_n, T[n * 3 + 1], h1);
        h2 = fmaf(r_n, T[n * 3 + 2], h2);
        float r_np1 = fmaf(twoc, r_n, -r_nm1);
        r_nm1 = r_n;
        r_n   = r_np1;
    }

    // shifted-cosine cutoff (rc=5, width=0.5)
    float fc;
    if (d < 4.5f) {
        fc = 1.0f;
    } else if (d < 5.0f) {
        fc = 0.5f * (__cosf(6.28318530717958647692f * (d - 4.5f)) + 1.0f);
    } else {
        fc = 0.0f;
    }

    float f  = fc * invd;
    float y0 = vy * f;   // m order (-1,0,1) -> (y,z,x)/d
    float y1 = vz * f;
    float y2 = vx * f;

    // padded m-row layout: rows m at +0,+4,+8; lane 3 = pad
    float* base = scratch + (size_t)a * 12;
    red_add_v4(base + 0, y0 * h0, y0 * h1, y0 * h2, 0.0f);
    red_add_v4(base + 4, y1 * h0, y1 * h1, y1 * h2, 0.0f);
    red_add_v4(base + 8, y2 * h0, y2 * h1, y2 * h2, 0.0f);
}

__global__ void __launch_bounds__(256)
mono_kernel(const float* __restrict__ vecs,     // (E,3)
            const int*   __restrict__ centers,  // (E,)
            const int*   __restrict__ neighbors,// (E,)
            const int*   __restrict__ species,  // (A,) int32 source
            const float* __restrict__ W_alch,   // (4,4)
            const float* __restrict__ emb,      // (4,32)
            const float* __restrict__ Wc,       // (3,32)
            float*       __restrict__ scratch,  // (A,12)
            unsigned char* __restrict__ spec8,  // (A,)
            float*       __restrict__ out,      // (A,9)
            int E, int A)
{
    cg::grid_group grid = cg::this_grid();
    int t    = threadIdx.x;
    int bid  = blockIdx.x;
    int nblk = gridDim.x;
    int gtid = bid * 256 + t;
    int nthr = nblk * 256;

    // ---- phase 0: pack species -> u8 (grid-stride, vectorized) ----
    int np = A >> 2;
    for (int i = gtid; i < np; i += nthr) {
        int4 sp = ((const int4*)species)[i];
        ((uchar4*)spec8)[i] = make_uchar4((unsigned char)sp.x, (unsigned char)sp.y,
                                          (unsigned char)sp.z, (unsigned char)sp.w);
    }
    if (gtid == 0) {
        for (int j = np * 4; j < A; j++) spec8[j] = (unsigned char)species[j];
    }

    // build per-block sT before the sync (independent of spec8)
    __shared__ float sT[16 * 25];
    if (t < 192) {
        int idx0 = t * 2;
#pragma unroll
        for (int u = 0; u < 2; u++) {
            int idx = idx0 + u;            // 0..383 = 16*24
            int p = idx / 24, r = idx - p * 24;
            int n = r / 3,  o = r - n * 3;
            int sc = p >> 2, sn = p & 3;
            float v = 0.f;
#pragma unroll
            for (int q = 0; q < 4; q++) {
                int dd = n * 4 + q;
                v = fmaf(W_alch[sn * 4 + q] * emb[sc * 32 + dd], Wc[o * 32 + dd], v);
            }
            sT[p * 25 + r] = v;
        }
    }

    grid.sync();   // spec8 ready (also block-syncs sT)

    // ---- phase 1: edge tiles (grid-stride; no state held across sync) ----
    int ntiles_full = E / EPB;
    int ntiles      = (E + EPB - 1) / EPB;
    for (int tile = bid; tile < ntiles; tile += nblk) {
        int e0   = tile * EPB;
        int base = e0 + t * 4;
        if (tile < ntiles_full) {
            const float4* v4 = (const float4*)(vecs + (size_t)e0 * 3);
            float4 va = v4[t * 3 + 0];
            float4 vb = v4[t * 3 + 1];
            float4 vc = v4[t * 3 + 2];
            int4 cc = *(const int4*)(centers   + base);
            int4 nn = *(const int4*)(neighbors + base);
            process_edge(va.x, va.y, va.z, cc.x, nn.x, spec8, sT, scratch);
            process_edge(va.w, vb.x, vb.y, cc.y, nn.y, spec8, sT, scratch);
            process_edge(vb.z, vb.w, vc.x, cc.z, nn.z, spec8, sT, scratch);
            process_edge(vc.y, vc.z, vc.w, cc.w, nn.w, spec8, sT, scratch);
        } else {
#pragma unroll
            for (int j = 0; j < 4; j++) {
                int e = base + j;
                if (e < E) {
                    float vx = vecs[(size_t)e * 3 + 0];
                    float vy = vecs[(size_t)e * 3 + 1];
                    float vz = vecs[(size_t)e * 3 + 2];
                    process_edge(vx, vy, vz, centers[e], neighbors[e], spec8, sT, scratch);
                }
            }
        }
    }

    __threadfence();   // order REDs before the barrier release
    grid.sync();       // all REDs visible

    // ---- phase 2: flat finalize + zero-writeback ----
    int nrows = A * 3;
    float4* scratch4 = (float4*)scratch;
    for (int i = gtid; i < nrows; i += nthr) {
        float4 v = scratch4[i];
        int a = i / 3;
        int m = i - a * 3;
        float* o = out + (size_t)a * 9 + m * 3;
        o[0] = v.x;
        o[1] = v.y;
        o[2] = v.z;
        scratch4[i] = make_float4(0.f, 0.f, 0.f, 0.f);
    }
}

extern "C" void kernel_launch(void* const* d_in, const int* in_sizes, int n_in,
                              void* d_out, int out_size)
{
    const float* vecs      = (const float*)d_in[0];
    const int*   centers   = (const int*)  d_in[1];
    const int*   neighbors = (const int*)  d_in[2];
    const int*   species   = (const int*)  d_in[3];
    // d_in[4], d_in[5] unused by reference
    const float* W_alch    = (const float*)d_in[6];
    const float* emb       = (const float*)d_in[7];
    const float* Wc        = (const float*)d_in[8];

    int E = in_sizes[1];
    int A = in_sizes[3];

    float* scratch = nullptr;
    cudaGetSymbolAddress((void**)&scratch, g_scratch);
    unsigned char* spec8 = nullptr;
    cudaGetSymbolAddress((void**)&spec8, g_spec8);
    float* outp = (float*)d_out;

    int dev = 0;
    cudaGetDevice(&dev);
    int sms = 0;
    cudaDeviceGetAttribute(&sms, cudaDevAttrMultiProcessorCount, dev);
    int maxb = 0;
    cudaOccupancyMaxActiveBlocksPerMultiprocessor(&maxb, mono_kernel, 256, 0);
    if (maxb < 1) maxb = 1;
    int grid = sms * maxb;

    void* args[] = {
        (void*)&vecs, (void*)&centers, (void*)&neighbors, (void*)&species,
        (void*)&W_alch, (void*)&emb, (void*)&Wc,
        (void*)&scratch, (void*)&spec8, (void*)&outp,
        (void*)&E, (void*)&A
    };
    cudaLaunchCooperativeKernel((const void*)mono_kernel,
                                dim3(grid), dim3(256), args, 0, (cudaStream_t)0);
}

// round 15
// speedup vs baseline: 1.4475x; 1.4475x over previous
#include <cuda_runtime.h>
#include <cstdint>

// ---------------------------------------------------------------------------
// VectorBasis: out[a,m,o] = sum_{edges e with center a}
//     fc(d_e) * Y_m(e) * sum_n R_n(d_e) * T[sc_a, sn_e, n, o]
// where T[sc,sn,n,o] = sum_q W_alch[sn,q] * emb[sc, n*4+q] * Wc[o, n*4+q]
//
// R15 = R12 (best, 36.9us) with 8 edges/thread (EPB=2048) to deepen load
//       MLP: 6x LDG.128 vecs + 2x LDG.128 centers + 2x LDG.128 neighbors
//       issued up front per thread. Everything else identical to R12.
// Pipeline: pack(u8) -> edge_8x -> finalize_wb.
// Scratch layout: padded m-rows scratch[a*12 + m*4 + o], lane 3 = pad.
// g_scratch zero at module load; finalize zero-writeback restores invariant.
// ---------------------------------------------------------------------------

#define A_MAX 100000
__device__ float         g_scratch[A_MAX * 12];
__device__ unsigned char g_spec8[A_MAX + 4];

__device__ __forceinline__ void red_add_v4(float* p, float a, float b, float c, float d) {
    asm volatile("red.global.add.v4.f32 [%0], {%1, %2, %3, %4};"
                 :: "l"(p), "f"(a), "f"(b), "f"(c), "f"(d)
                 : "memory");
}

// species int32 -> u8 pack (vectorized).
__global__ void __launch_bounds__(256)
pack_kernel(const int4* __restrict__ species4, const int* __restrict__ species,
            uchar4* __restrict__ spec8_4, unsigned char* __restrict__ spec8, int A)
{
    int i = blockIdx.x * blockDim.x + threadIdx.x;
    int np = A >> 2;
    if (i < np) {
        int4 s = species4[i];
        spec8_4[i] = make_uchar4((unsigned char)s.x, (unsigned char)s.y,
                                 (unsigned char)s.z, (unsigned char)s.w);
    }
    if (i == np) {
        for (int j = np * 4; j < A; j++) spec8[j] = (unsigned char)species[j];
    }
}

#define EPT 8              // edges per thread
#define EPB (256 * EPT)    // 2048 edges per block

__device__ __forceinline__ void process_edge(
    float vx, float vy, float vz, int a, int nb,
    const unsigned char* __restrict__ spec8,
    const float* __restrict__ sT,
    float* __restrict__ scratch)
{
    float d2   = fmaf(vx, vx, fmaf(vy, vy, vz * vz)) + 1e-12f;
    float invd = rsqrtf(d2);
    float d    = d2 * invd;

    int sc = (int)__ldg(&spec8[a]);
    int sn = (int)__ldg(&spec8[nb]);
    const float* T = &sT[(sc * 4 + sn) * 25];

    // R_n = sin(n*pi*d/rc)/d via scalar Chebyshev recurrence
    float s, c;
    __sincosf(0.62831853071795864769f * d, &s, &c);  // pi/5 * d
    float twoc = 2.0f * c;
    float r_nm1 = 0.0f;
    float r_n   = s * invd;

    float h0 = 0.f, h1 = 0.f, h2 = 0.f;
#pragma unroll
    for (int n = 0; n < 8; n++) {
        h0 = fmaf(r_n, T[n * 3 + 0], h0);
        h1 = fmaf(r_n, T[n * 3 + 1], h1);
        h2 = fmaf(r_n, T[n * 3 + 2], h2);
        float r_np1 = fmaf(twoc, r_n, -r_nm1);
        r_nm1 = r_n;
        r_n   = r_np1;
    }

    // shifted-cosine cutoff (rc=5, width=0.5)
    float fc;
    if (d < 4.5f) {
        fc = 1.0f;
    } else if (d < 5.0f) {
        fc = 0.5f * (__cosf(6.28318530717958647692f * (d - 4.5f)) + 1.0f);
    } else {
        fc = 0.0f;
    }

    float f  = fc * invd;
    float y0 = vy * f;   // m order (-1,0,1) -> (y,z,x)/d
    float y1 = vz * f;
    float y2 = vx * f;

    // padded m-row layout: rows m at +0,+4,+8; lane 3 = pad
    float* base = scratch + (size_t)a * 12;
    red_add_v4(base + 0, y0 * h0, y0 * h1, y0 * h2, 0.0f);
    red_add_v4(base + 4, y1 * h0, y1 * h1, y1 * h2, 0.0f);
    red_add_v4(base + 8, y2 * h0, y2 * h1, y2 * h2, 0.0f);
}

__global__ void __launch_bounds__(256)
edge_kernel(const float*         __restrict__ vecs,     // (E,3)
            const int*           __restrict__ centers,  // (E,)
            const int*           __restrict__ neighbors,// (E,)
            const unsigned char* __restrict__ spec8,    // (A,) packed
            const float*         __restrict__ W_alch,   // (4,4)
            const float*         __restrict__ emb,      // (4,32)
            const float*         __restrict__ Wc,       // (3,32)
            float*               __restrict__ scratch,  // (A,12)
            int E)
{
    // Per-species-pair contraction table, stride 25 (odd -> conflict-free).
    __shared__ float sT[16 * 25];
    {
        int t = threadIdx.x;
        if (t < 192) {
            int idx0 = t * 2;
#pragma unroll
            for (int u = 0; u < 2; u++) {
                int idx = idx0 + u;            // 0..383 = 16*24
                int p = idx / 24, r = idx - p * 24;
                int n = r / 3,  o = r - n * 3;
                int sc = p >> 2, sn = p & 3;
                float v = 0.f;
#pragma unroll
                for (int q = 0; q < 4; q++) {
                    int dd = n * 4 + q;
                    v = fmaf(W_alch[sn * 4 + q] * emb[sc * 32 + dd], Wc[o * 32 + dd], v);
                }
                sT[p * 25 + r] = v;
            }
        }
    }
    __syncthreads();

    int e0 = blockIdx.x * EPB;
    int t  = threadIdx.x;
    int base = e0 + t * EPT;

    if (e0 + EPB <= E) {
        // direct vectorized loads: thread t owns edges [base, base+8)
        const float4* v4 = (const float4*)(vecs + (size_t)e0 * 3);
        float4 w[6];
#pragma unroll
        for (int k = 0; k < 6; k++) w[k] = v4[t * 6 + k];
        int4 cc0 = *(const int4*)(centers   + base);
        int4 cc1 = *(const int4*)(centers   + base + 4);
        int4 nn0 = *(const int4*)(neighbors + base);
        int4 nn1 = *(const int4*)(neighbors + base + 4);

        process_edge(w[0].x, w[0].y, w[0].z, cc0.x, nn0.x, spec8, sT, scratch);
        process_edge(w[0].w, w[1].x, w[1].y, cc0.y, nn0.y, spec8, sT, scratch);
        process_edge(w[1].z, w[1].w, w[2].x, cc0.z, nn0.z, spec8, sT, scratch);
        process_edge(w[2].y, w[2].z, w[2].w, cc0.w, nn0.w, spec8, sT, scratch);
        process_edge(w[3].x, w[3].y, w[3].z, cc1.x, nn1.x, spec8, sT, scratch);
        process_edge(w[3].w, w[4].x, w[4].y, cc1.y, nn1.y, spec8, sT, scratch);
        process_edge(w[4].z, w[4].w, w[5].x, cc1.z, nn1.z, spec8, sT, scratch);
        process_edge(w[5].y, w[5].z, w[5].w, cc1.w, nn1.w, spec8, sT, scratch);
    } else {
#pragma unroll
        for (int j = 0; j < EPT; j++) {
            int e = base + j;
            if (e < E) {
                float vx = vecs[(size_t)e * 3 + 0];
                float vy = vecs[(size_t)e * 3 + 1];
                float vz = vecs[(size_t)e * 3 + 2];
                process_edge(vx, vy, vz, centers[e], neighbors[e], spec8, sT, scratch);
            }
        }
    }
}

// Flat finalize + zero-writeback: thread i owns scratch float4-row i
// (atom a = i/3, row m = i%3). Reads [h0,h1,h2,pad], writes 3 floats to
// out[a*9 + m*3 .. +2], zeroes the row.
__global__ void __launch_bounds__(256)
finalize_kernel(float4* __restrict__ scratch4, float* __restrict__ out, int nrows)
{
    int i = blockIdx.x * blockDim.x + threadIdx.x;
    if (i >= nrows) return;
    float4 v = scratch4[i];
    int a = i / 3;
    int m = i - a * 3;
    float* o = out + (size_t)a * 9 + m * 3;
    o[0] = v.x;
    o[1] = v.y;
    o[2] = v.z;
    scratch4[i] = make_float4(0.f, 0.f, 0.f, 0.f);
}

extern "C" void kernel_launch(void* const* d_in, const int* in_sizes, int n_in,
                              void* d_out, int out_size)
{
    const float* vecs      = (const float*)d_in[0];
    const int*   centers   = (const int*)  d_in[1];
    const int*   neighbors = (const int*)  d_in[2];
    const int*   species   = (const int*)  d_in[3];
    // d_in[4], d_in[5] unused by reference
    const float* W_alch    = (const float*)d_in[6];
    const float* emb       = (const float*)d_in[7];
    const float* Wc        = (const float*)d_in[8];

    int E = in_sizes[1];
    int A = in_sizes[3];

    float* scratch = nullptr;
    cudaGetSymbolAddress((void**)&scratch, g_scratch);
    unsigned char* spec8 = nullptr;
    cudaGetSymbolAddress((void**)&spec8, g_spec8);

    int pn = (A >> 2) + 1;
    pack_kernel<<<(pn + 255) / 256, 256>>>((const int4*)species, species,
                                           (uchar4*)spec8, spec8, A);

    int eblocks = (E + EPB - 1) / EPB;
    edge_kernel<<<eblocks, 256>>>(vecs, centers, neighbors, spec8,
                                  W_alch, emb, Wc, scratch, E);

    int nrows = A * 3;
    finalize_kernel<<<(nrows + 255) / 256, 256>>>((float4*)scratch, (float*)d_out, nrows);
}

// round 16
// speedup vs baseline: 1.4894x; 1.0289x over previous
#include <cuda_runtime.h>
#include <cstdint>

// ---------------------------------------------------------------------------
// VectorBasis: out[a,m,o] = sum_{edges e with center a}
//     fc(d_e) * Y_m(e) * sum_n R_n(d_e) * T[sc_a, sn_e, n, o]
// where T[sc,sn,n,o] = sum_q W_alch[sn,q] * emb[sc, n*4+q] * Wc[o, n*4+q]
//
// R16 = R12 (best, 36.9us: pack u8 -> edge_4x -> finalize_wb) with the
//       finalize kernel processing 2 scratch rows per thread (deeper MLP;
//       finalize was latency-bound at issue=12%).
// Edge kernel byte-identical to R12: 4 edges/thread, direct LDG.128 loads,
// scalar Chebyshev, 3x red.global.add.v4.f32 into padded (A,12) scratch.
// Scratch layout: padded m-rows scratch[a*12 + m*4 + o], lane 3 = pad.
// g_scratch zero at module load; finalize zero-writeback restores invariant.
// ---------------------------------------------------------------------------

#define A_MAX 100000
__device__ float         g_scratch[A_MAX * 12];
__device__ unsigned char g_spec8[A_MAX + 4];

__device__ __forceinline__ void red_add_v4(float* p, float a, float b, float c, float d) {
    asm volatile("red.global.add.v4.f32 [%0], {%1, %2, %3, %4};"
                 :: "l"(p), "f"(a), "f"(b), "f"(c), "f"(d)
                 : "memory");
}

// species int32 -> u8 pack (vectorized).
__global__ void __launch_bounds__(256)
pack_kernel(const int4* __restrict__ species4, const int* __restrict__ species,
            uchar4* __restrict__ spec8_4, unsigned char* __restrict__ spec8, int A)
{
    int i = blockIdx.x * blockDim.x + threadIdx.x;
    int np = A >> 2;
    if (i < np) {
        int4 s = species4[i];
        spec8_4[i] = make_uchar4((unsigned char)s.x, (unsigned char)s.y,
                                 (unsigned char)s.z, (unsigned char)s.w);
    }
    if (i == np) {
        for (int j = np * 4; j < A; j++) spec8[j] = (unsigned char)species[j];
    }
}

#define EPB 1024   // edges per block (256 threads x 4)

__device__ __forceinline__ void process_edge(
    float vx, float vy, float vz, int a, int nb,
    const unsigned char* __restrict__ spec8,
    const float* __restrict__ sT,
    float* __restrict__ scratch)
{
    float d2   = fmaf(vx, vx, fmaf(vy, vy, vz * vz)) + 1e-12f;
    float invd = rsqrtf(d2);
    float d    = d2 * invd;

    int sc = (int)__ldg(&spec8[a]);
    int sn = (int)__ldg(&spec8[nb]);
    const float* T = &sT[(sc * 4 + sn) * 25];

    // R_n = sin(n*pi*d/rc)/d via scalar Chebyshev recurrence
    float s, c;
    __sincosf(0.62831853071795864769f * d, &s, &c);  // pi/5 * d
    float twoc = 2.0f * c;
    float r_nm1 = 0.0f;
    float r_n   = s * invd;

    float h0 = 0.f, h1 = 0.f, h2 = 0.f;
#pragma unroll
    for (int n = 0; n < 8; n++) {
        h0 = fmaf(r_n, T[n * 3 + 0], h0);
        h1 = fmaf(r_n, T[n * 3 + 1], h1);
        h2 = fmaf(r_n, T[n * 3 + 2], h2);
        float r_np1 = fmaf(twoc, r_n, -r_nm1);
        r_nm1 = r_n;
        r_n   = r_np1;
    }

    // shifted-cosine cutoff (rc=5, width=0.5)
    float fc;
    if (d < 4.5f) {
        fc = 1.0f;
    } else if (d < 5.0f) {
        fc = 0.5f * (__cosf(6.28318530717958647692f * (d - 4.5f)) + 1.0f);
    } else {
        fc = 0.0f;
    }

    float f  = fc * invd;
    float y0 = vy * f;   // m order (-1,0,1) -> (y,z,x)/d
    float y1 = vz * f;
    float y2 = vx * f;

    // padded m-row layout: rows m at +0,+4,+8; lane 3 = pad
    float* base = scratch + (size_t)a * 12;
    red_add_v4(base + 0, y0 * h0, y0 * h1, y0 * h2, 0.0f);
    red_add_v4(base + 4, y1 * h0, y1 * h1, y1 * h2, 0.0f);
    red_add_v4(base + 8, y2 * h0, y2 * h1, y2 * h2, 0.0f);
}

__global__ void __launch_bounds__(256)
edge_kernel(const float*         __restrict__ vecs,     // (E,3)
            const int*           __restrict__ centers,  // (E,)
            const int*           __restrict__ neighbors,// (E,)
            const unsigned char* __restrict__ spec8,    // (A,) packed
            const float*         __restrict__ W_alch,   // (4,4)
            const float*         __restrict__ emb,      // (4,32)
            const float*         __restrict__ Wc,       // (3,32)
            float*               __restrict__ scratch,  // (A,12)
            int E)
{
    // Per-species-pair contraction table, stride 25 (odd -> conflict-free).
    __shared__ float sT[16 * 25];
    {
        int t = threadIdx.x;
        if (t < 192) {
            int idx0 = t * 2;
#pragma unroll
            for (int u = 0; u < 2; u++) {
                int idx = idx0 + u;            // 0..383 = 16*24
                int p = idx / 24, r = idx - p * 24;
                int n = r / 3,  o = r - n * 3;
                int sc = p >> 2, sn = p & 3;
                float v = 0.f;
#pragma unroll
                for (int q = 0; q < 4; q++) {
                    int dd = n * 4 + q;
                    v = fmaf(W_alch[sn * 4 + q] * emb[sc * 32 + dd], Wc[o * 32 + dd], v);
                }
                sT[p * 25 + r] = v;
            }
        }
    }
    __syncthreads();

    int e0 = blockIdx.x * EPB;
    int t  = threadIdx.x;
    int base = e0 + t * 4;

    if (e0 + EPB <= E) {
        // direct vectorized loads: thread t owns edges [base, base+4)
        const float4* v4 = (const float4*)(vecs + (size_t)e0 * 3);
        float4 va = v4[t * 3 + 0];
        float4 vb = v4[t * 3 + 1];
        float4 vc = v4[t * 3 + 2];
        int4 cc = *(const int4*)(centers   + base);
        int4 nn = *(const int4*)(neighbors + base);
        process_edge(va.x, va.y, va.z, cc.x, nn.x, spec8, sT, scratch);
        process_edge(va.w, vb.x, vb.y, cc.y, nn.y, spec8, sT, scratch);
        process_edge(vb.z, vb.w, vc.x, cc.z, nn.z, spec8, sT, scratch);
        process_edge(vc.y, vc.z, vc.w, cc.w, nn.w, spec8, sT, scratch);
    } else {
#pragma unroll
        for (int j = 0; j < 4; j++) {
            int e = base + j;
            if (e < E) {
                float vx = vecs[(size_t)e * 3 + 0];
                float vy = vecs[(size_t)e * 3 + 1];
                float vz = vecs[(size_t)e * 3 + 2];
                process_edge(vx, vy, vz, centers[e], neighbors[e], spec8, sT, scratch);
            }
        }
    }
}

// Flat finalize + zero-writeback, 2 rows/thread for deeper MLP.
// Row i: atom a = i/3, m = i%3; out[a*9 + m*3 .. +2] = scratch row; zero row.
__global__ void __launch_bounds__(256)
finalize_kernel(float4* __restrict__ scratch4, float* __restrict__ out, int nrows)
{
    int i0 = (blockIdx.x * blockDim.x + threadIdx.x) * 2;
    const float4 z4 = make_float4(0.f, 0.f, 0.f, 0.f);

    // issue both loads before either store (MLP=2)
    float4 v0, v1;
    bool ok0 = (i0     < nrows);
    bool ok1 = (i0 + 1 < nrows);
    if (ok0) v0 = scratch4[i0];
    if (ok1) v1 = scratch4[i0 + 1];

    if (ok0) {
        int a = i0 / 3;
        int m = i0 - a * 3;
        float* o = out + (size_t)a * 9 + m * 3;
        o[0] = v0.x; o[1] = v0.y; o[2] = v0.z;
        scratch4[i0] = z4;
    }
    if (ok1) {
        int i = i0 + 1;
        int a = i / 3;
        int m = i - a * 3;
        float* o = out + (size_t)a * 9 + m * 3;
        o[0] = v1.x; o[1] = v1.y; o[2] = v1.z;
        scratch4[i] = z4;
    }
}

extern "C" void kernel_launch(void* const* d_in, const int* in_sizes, int n_in,
                              void* d_out, int out_size)
{
    const float* vecs      = (const float*)d_in[0];
    const int*   centers   = (const int*)  d_in[1];
    const int*   neighbors = (const int*)  d_in[2];
    const int*   species   = (const int*)  d_in[3];
    // d_in[4], d_in[5] unused by reference
    const float* W_alch    = (const float*)d_in[6];
    const float* emb       = (const float*)d_in[7];
    const float* Wc        = (const float*)d_in[8];

    int E = in_sizes[1];
    int A = in_sizes[3];

    float* scratch = nullptr;
    cudaGetSymbolAddress((void**)&scratch, g_scratch);
    unsigned char* spec8 = nullptr;
    cudaGetSymbolAddress((void**)&spec8, g_spec8);

    int pn = (A >> 2) + 1;
    pack_kernel<<<(pn + 255) / 256, 256>>>((const int4*)species, species,
                                           (uchar4*)spec8, spec8, A);

    int eblocks = (E + EPB - 1) / EPB;
    edge_kernel<<<eblocks, 256>>>(vecs, centers, neighbors, spec8,
                                  W_alch, emb, Wc, scratch, E);

    int nrows   = A * 3;
    int fthreads = (nrows + 1) / 2;
    finalize_kernel<<<(fthreads + 255) / 256, 256>>>((float4*)scratch, (float*)d_out, nrows);
}